// round 1
// baseline (speedup 1.0000x reference)
#include <cuda_runtime.h>
#include <math.h>

#define NN 2000
#define TT 64
#define HH 64
#define KK 10
#define PD 32
#define EF 32000
#define EK (NN*KK)
#define EE (EF+EK)

// ---------------- scratch (static __device__, no allocation) ----------------
__device__ float g_e[NN*PD];          // normalized embeddings
__device__ int   g_knn_dst[EK];
__device__ float g_knn_w[EK];         // vals * alpha
__device__ int   g_deg[NN];
__device__ int   g_rowstart[NN+1];
__device__ int   g_cursor[NN];
__device__ int   g_csr_src[EE];
__device__ float g_csr_w[EE];
__device__ float g_y[(size_t)NN*TT*HH];   // xt @ Wmsg^T + b  (32 MB, L2-resident)
__device__ float g_p[NN*TT];          // xt . att_src + b
__device__ float g_q[NN*TT];          // xt . att_dst + b

// ---------------- K1: x_agg -> e (normalized) ----------------
__global__ void k_embed(const float* __restrict__ x, const float* __restrict__ npw) {
    int n = blockIdx.x; int h = threadIdx.x;      // 64 threads
    __shared__ float xa[HH];
    __shared__ float ev[PD];
    const float* xp = x + (size_t)n*TT*HH + h;
    float s = 0.f;
    #pragma unroll
    for (int t = 0; t < TT; t++) s += xp[t*HH];
    xa[h] = s * (1.0f/TT);
    __syncthreads();
    if (h < PD) {
        float acc = 0.f;
        #pragma unroll
        for (int c = 0; c < HH; c++) acc += xa[c] * npw[h*HH + c];
        ev[h] = acc;
    }
    __syncthreads();
    if (h < PD) {                                  // h<32 == full warp 0
        float v = ev[h];
        float ss = v*v;
        #pragma unroll
        for (int o = 16; o > 0; o >>= 1) ss += __shfl_xor_sync(0xffffffffu, ss, o);
        float nrm = fmaxf(sqrtf(ss), 1e-12f);
        g_e[n*PD + h] = v / nrm;
    }
}

// ---------------- K2: per-row top-(K+1), drop self ----------------
__global__ void k_topk(const float* __restrict__ mix_logit) {
    int i = blockIdx.x; int tid = threadIdx.x;    // 256 threads
    __shared__ float sim[NN];
    __shared__ float ei[PD];
    __shared__ float rv[256];
    __shared__ int   ri[256];
    if (tid < PD) ei[tid] = g_e[i*PD + tid];
    __syncthreads();
    for (int j = tid; j < NN; j += 256) {
        const float* ej = g_e + j*PD;
        float d = 0.f;
        #pragma unroll
        for (int c = 0; c < PD; c++) d += ei[c]*ej[c];
        sim[j] = d;
    }
    __syncthreads();
    float alpha = 1.f/(1.f + expf(-mix_logit[0]));
    for (int k = 0; k <= KK; k++) {
        float bv = -INFINITY; int bi = NN;
        for (int j = tid; j < NN; j += 256) {
            float v = sim[j];
            if (v > bv || (v == bv && j < bi)) { bv = v; bi = j; }
        }
        rv[tid] = bv; ri[tid] = bi;
        __syncthreads();
        for (int s = 128; s > 0; s >>= 1) {
            if (tid < s) {
                float v2 = rv[tid+s]; int i2 = ri[tid+s];
                if (v2 > rv[tid] || (v2 == rv[tid] && i2 < ri[tid])) { rv[tid] = v2; ri[tid] = i2; }
            }
            __syncthreads();
        }
        if (tid == 0) {
            int j = ri[0];
            if (k > 0) { g_knn_dst[i*KK + (k-1)] = j; g_knn_w[i*KK + (k-1)] = rv[0]*alpha; }
            sim[j] = -INFINITY;
        }
        __syncthreads();
    }
}

// ---------------- CSR build ----------------
__global__ void k_zero_deg() {
    int i = blockIdx.x*blockDim.x + threadIdx.x;
    if (i < NN) g_deg[i] = 0;
}

__global__ void k_deg(const int* __restrict__ fei) {
    int e = blockIdx.x*blockDim.x + threadIdx.x;
    if (e >= EE) return;
    int d = (e < EF) ? fei[EF + e] : g_knn_dst[e - EF];
    atomicAdd(&g_deg[d], 1);
}

__global__ void k_scan() {                         // 1 block, 1024 threads
    __shared__ int a[2048], b[2048];
    int tid = threadIdx.x;
    for (int i = tid; i < 2048; i += 1024) a[i] = (i < NN) ? g_deg[i] : 0;
    __syncthreads();
    int* in = a; int* out = b;
    for (int off = 1; off < 2048; off <<= 1) {
        for (int i = tid; i < 2048; i += 1024)
            out[i] = in[i] + (i >= off ? in[i-off] : 0);
        __syncthreads();
        int* t = in; in = out; out = t;
    }
    for (int i = tid; i <= NN; i += 1024) {
        int rs = (i == 0) ? 0 : in[i-1];
        g_rowstart[i] = rs;
        if (i < NN) g_cursor[i] = rs;
    }
}

__global__ void k_scatter(const int* __restrict__ fei, const float* __restrict__ fea,
                          const float* __restrict__ mix_logit) {
    int e = blockIdx.x*blockDim.x + threadIdx.x;
    if (e >= EE) return;
    float alpha = 1.f/(1.f + expf(-mix_logit[0]));
    int s, d; float w;
    if (e < EF) { s = fei[e]; d = fei[EF + e]; w = fea[e]*(1.f - alpha); }
    else { int ke = e - EF; s = ke / KK; d = g_knn_dst[ke]; w = g_knn_w[ke]; }
    int pos = atomicAdd(&g_cursor[d], 1);
    g_csr_src[pos] = s; g_csr_w[pos] = w;
}

// ---------------- K3: fused tconv -> (y, p, q) + self term ----------------
__global__ void __launch_bounds__(256) k_node(
    const float* __restrict__ x,
    const float* __restrict__ tw,  const float* __restrict__ tb,
    const float* __restrict__ lmw, const float* __restrict__ lmb,
    const float* __restrict__ lsw, const float* __restrict__ lsb,
    const float* __restrict__ asw, const float* __restrict__ asb,
    const float* __restrict__ adw, const float* __restrict__ adb,
    float* __restrict__ out)
{
    int n = blockIdx.x;
    int tid = threadIdx.x;
    int o = tid & 63, tc = tid >> 6;
    int base = tc * 16;
    __shared__ float xs[(TT+2)*HH];   // time rows padded (-1 .. T)
    __shared__ float xts[TT*HH];      // conv output

    const float* xn = x + (size_t)n*TT*HH;
    for (int idx = tid; idx < TT*HH; idx += 256) xs[idx + HH] = xn[idx];
    for (int idx = tid; idx < HH; idx += 256) { xs[idx] = 0.f; xs[(TT+1)*HH + idx] = 0.f; }
    __syncthreads();

    // temporal conv: xt[t,o] = b[o] + sum_{i,k} x[t+k-1,i] * w[o,i,k]
    float acc[16];
    #pragma unroll
    for (int tt = 0; tt < 16; tt++) acc[tt] = 0.f;
    for (int i = 0; i < HH; i++) {
        float w0 = tw[o*192 + i*3 + 0];
        float w1 = tw[o*192 + i*3 + 1];
        float w2 = tw[o*192 + i*3 + 2];
        float vm = xs[base*HH + i];
        float vc = xs[(base+1)*HH + i];
        #pragma unroll
        for (int tt = 0; tt < 16; tt++) {
            float vp = xs[(base+tt+2)*HH + i];
            acc[tt] += vm*w0 + vc*w1 + vp*w2;
            vm = vc; vc = vp;
        }
    }
    float bo = tb[o];
    #pragma unroll
    for (int tt = 0; tt < 16; tt++) xts[(base+tt)*HH + o] = acc[tt] + bo;
    __syncthreads();

    // y = xt @ Wmsg^T + bmsg
    float yb = lmb[o];
    #pragma unroll
    for (int tt = 0; tt < 16; tt++) acc[tt] = yb;
    for (int i = 0; i < HH; i++) {
        float w = lmw[o*HH + i];
        #pragma unroll
        for (int tt = 0; tt < 16; tt++) acc[tt] += xts[(base+tt)*HH + i]*w;
    }
    float* yp = g_y + (size_t)n*TT*HH;
    #pragma unroll
    for (int tt = 0; tt < 16; tt++) yp[(base+tt)*HH + o] = acc[tt];

    // self term straight into out: x @ Wself^T + bself
    float sb = lsb[o];
    #pragma unroll
    for (int tt = 0; tt < 16; tt++) acc[tt] = sb;
    for (int i = 0; i < HH; i++) {
        float w = lsw[o*HH + i];
        #pragma unroll
        for (int tt = 0; tt < 16; tt++) acc[tt] += xs[(base+tt+1)*HH + i]*w;
    }
    float* op = out + (size_t)n*TT*HH;
    #pragma unroll
    for (int tt = 0; tt < 16; tt++) op[(base+tt)*HH + o] = acc[tt];

    // p, q: warp-per-8-timesteps reductions over xts
    int warp = tid >> 5, lane = tid & 31;
    float asb0 = asb[0], adb0 = adb[0];
    float aw1 = asw[lane], aw2 = asw[lane+32];
    float dw1 = adw[lane], dw2 = adw[lane+32];
    for (int tt = 0; tt < 8; tt++) {
        int t = warp*8 + tt;
        float v1 = xts[t*HH + lane], v2 = xts[t*HH + lane + 32];
        float pp = v1*aw1 + v2*aw2;
        float qq = v1*dw1 + v2*dw2;
        #pragma unroll
        for (int off = 16; off > 0; off >>= 1) {
            pp += __shfl_down_sync(0xffffffffu, pp, off);
            qq += __shfl_down_sync(0xffffffffu, qq, off);
        }
        if (lane == 0) { g_p[n*TT + t] = pp + asb0; g_q[n*TT + t] = qq + adb0; }
    }
}

// ---------------- K4: per-dst softmax + weighted aggregation ----------------
__global__ void __launch_bounds__(256) k_aggr(float* __restrict__ out) {
    int d = blockIdx.x; int tid = threadIdx.x;
    __shared__ float S[TT*HH];
    __shared__ float coef[TT];
    __shared__ float zs[TT];
    __shared__ float ms[TT];
    __shared__ float qv[TT];
    int r0 = g_rowstart[d], r1 = g_rowstart[d+1];
    for (int idx = tid; idx < TT*HH; idx += 256) S[idx] = 0.f;
    if (tid < TT) qv[tid] = g_q[d*TT + tid];
    __syncthreads();

    // pass 1: per-t max over edges
    if (tid < TT) {
        float m = -INFINITY;
        for (int e = r0; e < r1; e++) {
            int s = g_csr_src[e];
            float a = g_p[s*TT + tid] + qv[tid];
            a = a > 0.f ? a : 0.2f*a;
            m = fmaxf(m, a);
        }
        ms[tid] = m;
    }
    __syncthreads();

    // pass 2: accumulate exp(a-m)*ea*y[s]
    float z = 0.f;
    float4* S4 = (float4*)S;
    const float4* Y4 = (const float4*)g_y;
    for (int e = r0; e < r1; e++) {
        int s = g_csr_src[e];
        if (tid < TT) {
            float a = g_p[s*TT + tid] + qv[tid];
            a = a > 0.f ? a : 0.2f*a;
            float c = __expf(a - ms[tid]);
            z += c;
            coef[tid] = c * g_csr_w[e];
        }
        __syncthreads();
        const float4* ys = Y4 + (size_t)s*(TT*HH/4);
        for (int idx4 = tid; idx4 < TT*HH/4; idx4 += 256) {
            int t = idx4 >> 4;
            float c = coef[t];
            float4 yv = ys[idx4];
            float4 sv = S4[idx4];
            sv.x += c*yv.x; sv.y += c*yv.y; sv.z += c*yv.z; sv.w += c*yv.w;
            S4[idx4] = sv;
        }
        __syncthreads();
    }
    if (tid < TT) zs[tid] = z;
    __syncthreads();

    if (r1 > r0) {
        float4* O4 = (float4*)(out + (size_t)d*TT*HH);
        for (int idx4 = tid; idx4 < TT*HH/4; idx4 += 256) {
            int t = idx4 >> 4;
            float inv = 1.f/(zs[t] + 1e-16f);
            float4 sv = S4[idx4]; float4 ov = O4[idx4];
            ov.x += sv.x*inv; ov.y += sv.y*inv; ov.z += sv.z*inv; ov.w += sv.w*inv;
            O4[idx4] = ov;
        }
    }
}

// ---------------- launch ----------------
extern "C" void kernel_launch(void* const* d_in, const int* in_sizes, int n_in,
                              void* d_out, int out_size) {
    const float* x   = (const float*)d_in[0];
    const int*   fei = (const int*)  d_in[1];
    const float* fea = (const float*)d_in[2];
    const float* npw = (const float*)d_in[3];
    const float* ml  = (const float*)d_in[4];
    const float* tw  = (const float*)d_in[5];
    const float* tb  = (const float*)d_in[6];
    const float* lmw = (const float*)d_in[7];
    const float* lmb = (const float*)d_in[8];
    const float* lsw = (const float*)d_in[9];
    const float* lsb = (const float*)d_in[10];
    const float* asw = (const float*)d_in[11];
    const float* asb = (const float*)d_in[12];
    const float* adw = (const float*)d_in[13];
    const float* adb = (const float*)d_in[14];
    float* out = (float*)d_out;

    k_embed  <<<NN, 64>>>(x, npw);
    k_topk   <<<NN, 256>>>(ml);
    k_zero_deg<<<(NN+255)/256, 256>>>();
    k_deg    <<<(EE+255)/256, 256>>>(fei);
    k_scan   <<<1, 1024>>>();
    k_scatter<<<(EE+255)/256, 256>>>(fei, fea, ml);
    k_node   <<<NN, 256>>>(x, tw, tb, lmw, lmb, lsw, lsb, asw, asb, adw, adb, out);
    k_aggr   <<<NN, 256>>>(out);
}

// round 2
// speedup vs baseline: 1.5874x; 1.5874x over previous
#include <cuda_runtime.h>
#include <math.h>

#define NN 2000
#define TT 64
#define HH 64
#define KK 10
#define PD 32
#define EF 32000
#define EK (NN*KK)
#define EE (EF+EK)

// ---------------- scratch (static __device__, no allocation) ----------------
__device__ float g_e[NN*PD];          // normalized embeddings
__device__ int   g_knn_dst[EK];
__device__ float g_knn_w[EK];         // vals * alpha
__device__ int   g_deg[NN];
__device__ int   g_rowstart[NN+1];
__device__ int   g_cursor[NN];
__device__ int   g_csr_src[EE];
__device__ float g_csr_w[EE];
__device__ float g_y[(size_t)NN*TT*HH];   // xt @ Wmsg^T + b  (32 MB, L2-resident)
__device__ float g_p[NN*TT];          // xt . att_src + b
__device__ float g_q[NN*TT];          // xt . att_dst + b

// ---------------- K1: x_agg -> e (normalized) ----------------
__global__ void k_embed(const float* __restrict__ x, const float* __restrict__ npw) {
    int n = blockIdx.x; int h = threadIdx.x;      // 64 threads
    __shared__ float xa[HH];
    __shared__ float ev[PD];
    const float* xp = x + (size_t)n*TT*HH + h;
    float s = 0.f;
    #pragma unroll
    for (int t = 0; t < TT; t++) s += xp[t*HH];
    xa[h] = s * (1.0f/TT);
    __syncthreads();
    if (h < PD) {
        float acc = 0.f;
        #pragma unroll
        for (int c = 0; c < HH; c++) acc += xa[c] * npw[h*HH + c];
        ev[h] = acc;
    }
    __syncthreads();
    if (h < PD) {                                  // h<32 == full warp 0
        float v = ev[h];
        float ss = v*v;
        #pragma unroll
        for (int o = 16; o > 0; o >>= 1) ss += __shfl_xor_sync(0xffffffffu, ss, o);
        float nrm = fmaxf(sqrtf(ss), 1e-12f);
        g_e[n*PD + h] = v / nrm;
    }
}

// ---------------- K2: per-row top-(K+1), drop self ----------------
__global__ void k_topk(const float* __restrict__ mix_logit) {
    int i = blockIdx.x; int tid = threadIdx.x;    // 256 threads
    __shared__ float sim[NN];
    __shared__ float ei[PD];
    __shared__ float rv[256];
    __shared__ int   ri[256];
    if (tid < PD) ei[tid] = g_e[i*PD + tid];
    __syncthreads();
    for (int j = tid; j < NN; j += 256) {
        const float* ej = g_e + j*PD;
        float d = 0.f;
        #pragma unroll
        for (int c = 0; c < PD; c++) d += ei[c]*ej[c];
        sim[j] = d;
    }
    __syncthreads();
    float alpha = 1.f/(1.f + expf(-mix_logit[0]));
    for (int k = 0; k <= KK; k++) {
        float bv = -INFINITY; int bi = NN;
        for (int j = tid; j < NN; j += 256) {
            float v = sim[j];
            if (v > bv || (v == bv && j < bi)) { bv = v; bi = j; }
        }
        rv[tid] = bv; ri[tid] = bi;
        __syncthreads();
        for (int s = 128; s > 0; s >>= 1) {
            if (tid < s) {
                float v2 = rv[tid+s]; int i2 = ri[tid+s];
                if (v2 > rv[tid] || (v2 == rv[tid] && i2 < ri[tid])) { rv[tid] = v2; ri[tid] = i2; }
            }
            __syncthreads();
        }
        if (tid == 0) {
            int j = ri[0];
            if (k > 0) { g_knn_dst[i*KK + (k-1)] = j; g_knn_w[i*KK + (k-1)] = rv[0]*alpha; }
            sim[j] = -INFINITY;
        }
        __syncthreads();
    }
}

// ---------------- CSR build ----------------
__global__ void k_zero_deg() {
    int i = blockIdx.x*blockDim.x + threadIdx.x;
    if (i < NN) g_deg[i] = 0;
}

__global__ void k_deg(const int* __restrict__ fei) {
    int e = blockIdx.x*blockDim.x + threadIdx.x;
    if (e >= EE) return;
    int d = (e < EF) ? fei[EF + e] : g_knn_dst[e - EF];
    atomicAdd(&g_deg[d], 1);
}

__global__ void k_scan() {                         // 1 block, 1024 threads
    __shared__ int a[2048], b[2048];
    int tid = threadIdx.x;
    for (int i = tid; i < 2048; i += 1024) a[i] = (i < NN) ? g_deg[i] : 0;
    __syncthreads();
    int* in = a; int* out = b;
    for (int off = 1; off < 2048; off <<= 1) {
        for (int i = tid; i < 2048; i += 1024)
            out[i] = in[i] + (i >= off ? in[i-off] : 0);
        __syncthreads();
        int* t = in; in = out; out = t;
    }
    for (int i = tid; i <= NN; i += 1024) {
        int rs = (i == 0) ? 0 : in[i-1];
        g_rowstart[i] = rs;
        if (i < NN) g_cursor[i] = rs;
    }
}

__global__ void k_scatter(const int* __restrict__ fei, const float* __restrict__ fea,
                          const float* __restrict__ mix_logit) {
    int e = blockIdx.x*blockDim.x + threadIdx.x;
    if (e >= EE) return;
    float alpha = 1.f/(1.f + expf(-mix_logit[0]));
    int s, d; float w;
    if (e < EF) { s = fei[e]; d = fei[EF + e]; w = fea[e]*(1.f - alpha); }
    else { int ke = e - EF; s = ke / KK; d = g_knn_dst[ke]; w = g_knn_w[ke]; }
    int pos = atomicAdd(&g_cursor[d], 1);
    g_csr_src[pos] = s; g_csr_w[pos] = w;
}

// ---------------- K3: fused tconv -> (y, p, q) + self term ----------------
// Dynamic smem layout (floats):
//   xs   [0 .. 4224)              input with +-1 time halo: (TT+2)*HH
//   xts  [4224 .. 8320)           conv output TT*HH
//   wbuf [8320 .. 8320+12480)     transposed+padded weights, reused 3x (stride 65)
#define XS_OFF   0
#define XTS_OFF  ((TT+2)*HH)
#define WB_OFF   (XTS_OFF + TT*HH)
#define SM_FLOATS (WB_OFF + 192*65)
#define SM_BYTES  (SM_FLOATS*4)

__global__ void __launch_bounds__(256) k_node(
    const float* __restrict__ x,
    const float* __restrict__ tw,  const float* __restrict__ tb,
    const float* __restrict__ lmw, const float* __restrict__ lmb,
    const float* __restrict__ lsw, const float* __restrict__ lsb,
    const float* __restrict__ asw, const float* __restrict__ asb,
    const float* __restrict__ adw, const float* __restrict__ adb,
    float* __restrict__ out)
{
    extern __shared__ float sm[];
    float* xs  = sm + XS_OFF;
    float* xts = sm + XTS_OFF;
    float* wb  = sm + WB_OFF;

    int n = blockIdx.x;
    int tid = threadIdx.x;
    int o = tid & 63, tc = tid >> 6;
    int base = tc * 16;

    // phase 1: load x (with halo) + stage lsw transposed (coalesced global reads)
    const float* xn = x + (size_t)n*TT*HH;
    for (int idx = tid; idx < TT*HH; idx += 256) xs[idx + HH] = xn[idx];
    for (int idx = tid; idx < HH; idx += 256) { xs[idx] = 0.f; xs[(TT+1)*HH + idx] = 0.f; }
    #pragma unroll
    for (int it = 0; it < 16; it++) {             // 4096 elems
        int idx = it*256 + tid;
        int oo = idx >> 6, ii = idx & 63;
        wb[ii*65 + oo] = lsw[idx];
    }
    __syncthreads();

    float acc[16];

    // phase 2: self term -> out : x @ Wself^T + b
    float sb = lsb[o];
    #pragma unroll
    for (int tt = 0; tt < 16; tt++) acc[tt] = sb;
    for (int i = 0; i < HH; i++) {
        float w = wb[i*65 + o];                   // conflict-free
        #pragma unroll
        for (int tt = 0; tt < 16; tt++) acc[tt] += xs[(base+tt+1)*HH + i]*w;  // broadcast
    }
    float* op = out + (size_t)n*TT*HH;
    #pragma unroll
    for (int tt = 0; tt < 16; tt++) op[(base+tt)*HH + o] = acc[tt];
    __syncthreads();

    // phase 3: stage tconv weights transposed: wb[(i*3+k)*65 + o] = tw[o*192 + i*3+k]
    #pragma unroll
    for (int it = 0; it < 48; it++) {             // 12288 elems
        int idx = it*256 + tid;
        int oo = idx / 192, rr = idx - oo*192;
        wb[rr*65 + oo] = tw[idx];
    }
    __syncthreads();

    // phase 4: temporal conv: xt[t,o] = b[o] + sum_{i,k} x[t+k-1,i]*w[o,i,k]
    #pragma unroll
    for (int tt = 0; tt < 16; tt++) acc[tt] = 0.f;
    for (int i = 0; i < HH; i++) {
        float w0 = wb[(i*3+0)*65 + o];
        float w1 = wb[(i*3+1)*65 + o];
        float w2 = wb[(i*3+2)*65 + o];
        float vm = xs[base*HH + i];
        float vc = xs[(base+1)*HH + i];
        #pragma unroll
        for (int tt = 0; tt < 16; tt++) {
            float vp = xs[(base+tt+2)*HH + i];
            acc[tt] += vm*w0 + vc*w1 + vp*w2;
            vm = vc; vc = vp;
        }
    }
    float bo = tb[o];
    #pragma unroll
    for (int tt = 0; tt < 16; tt++) xts[(base+tt)*HH + o] = acc[tt] + bo;
    __syncthreads();

    // phase 5: stage lmw transposed
    #pragma unroll
    for (int it = 0; it < 16; it++) {
        int idx = it*256 + tid;
        int oo = idx >> 6, ii = idx & 63;
        wb[ii*65 + oo] = lmw[idx];
    }
    __syncthreads();

    // phase 6: y = xt @ Wmsg^T + b  -> g_y
    float yb = lmb[o];
    #pragma unroll
    for (int tt = 0; tt < 16; tt++) acc[tt] = yb;
    for (int i = 0; i < HH; i++) {
        float w = wb[i*65 + o];
        #pragma unroll
        for (int tt = 0; tt < 16; tt++) acc[tt] += xts[(base+tt)*HH + i]*w;
    }
    float* yp = g_y + (size_t)n*TT*HH;
    #pragma unroll
    for (int tt = 0; tt < 16; tt++) yp[(base+tt)*HH + o] = acc[tt];

    // phase 7: p, q: warp-per-8-timesteps reductions over xts
    int warp = tid >> 5, lane = tid & 31;
    float asb0 = asb[0], adb0 = adb[0];
    float aw1 = asw[lane], aw2 = asw[lane+32];
    float dw1 = adw[lane], dw2 = adw[lane+32];
    for (int tt = 0; tt < 8; tt++) {
        int t = warp*8 + tt;
        float v1 = xts[t*HH + lane], v2 = xts[t*HH + lane + 32];
        float pp = v1*aw1 + v2*aw2;
        float qq = v1*dw1 + v2*dw2;
        #pragma unroll
        for (int off = 16; off > 0; off >>= 1) {
            pp += __shfl_down_sync(0xffffffffu, pp, off);
            qq += __shfl_down_sync(0xffffffffu, qq, off);
        }
        if (lane == 0) { g_p[n*TT + t] = pp + asb0; g_q[n*TT + t] = qq + adb0; }
    }
}

// ---------------- K4: per-dst softmax + weighted aggregation ----------------
__global__ void __launch_bounds__(256) k_aggr(float* __restrict__ out) {
    int d = blockIdx.x; int tid = threadIdx.x;
    __shared__ float S[TT*HH];
    __shared__ float coef[TT];
    __shared__ float zs[TT];
    __shared__ float ms[TT];
    __shared__ float qv[TT];
    int r0 = g_rowstart[d], r1 = g_rowstart[d+1];
    for (int idx = tid; idx < TT*HH; idx += 256) S[idx] = 0.f;
    if (tid < TT) qv[tid] = g_q[d*TT + tid];
    __syncthreads();

    // pass 1: per-t max over edges
    if (tid < TT) {
        float m = -INFINITY;
        for (int e = r0; e < r1; e++) {
            int s = g_csr_src[e];
            float a = g_p[s*TT + tid] + qv[tid];
            a = a > 0.f ? a : 0.2f*a;
            m = fmaxf(m, a);
        }
        ms[tid] = m;
    }
    __syncthreads();

    // pass 2: accumulate exp(a-m)*ea*y[s]
    float z = 0.f;
    float4* S4 = (float4*)S;
    const float4* Y4 = (const float4*)g_y;
    for (int e = r0; e < r1; e++) {
        int s = g_csr_src[e];
        if (tid < TT) {
            float a = g_p[s*TT + tid] + qv[tid];
            a = a > 0.f ? a : 0.2f*a;
            float c = __expf(a - ms[tid]);
            z += c;
            coef[tid] = c * g_csr_w[e];
        }
        __syncthreads();
        const float4* ys = Y4 + (size_t)s*(TT*HH/4);
        for (int idx4 = tid; idx4 < TT*HH/4; idx4 += 256) {
            int t = idx4 >> 4;
            float c = coef[t];
            float4 yv = ys[idx4];
            float4 sv = S4[idx4];
            sv.x += c*yv.x; sv.y += c*yv.y; sv.z += c*yv.z; sv.w += c*yv.w;
            S4[idx4] = sv;
        }
        __syncthreads();
    }
    if (tid < TT) zs[tid] = z;
    __syncthreads();

    if (r1 > r0) {
        float4* O4 = (float4*)(out + (size_t)d*TT*HH);
        for (int idx4 = tid; idx4 < TT*HH/4; idx4 += 256) {
            int t = idx4 >> 4;
            float inv = 1.f/(zs[t] + 1e-16f);
            float4 sv = S4[idx4]; float4 ov = O4[idx4];
            ov.x += sv.x*inv; ov.y += sv.y*inv; ov.z += sv.z*inv; ov.w += sv.w*inv;
            O4[idx4] = ov;
        }
    }
}

// ---------------- launch ----------------
extern "C" void kernel_launch(void* const* d_in, const int* in_sizes, int n_in,
                              void* d_out, int out_size) {
    const float* x   = (const float*)d_in[0];
    const int*   fei = (const int*)  d_in[1];
    const float* fea = (const float*)d_in[2];
    const float* npw = (const float*)d_in[3];
    const float* ml  = (const float*)d_in[4];
    const float* tw  = (const float*)d_in[5];
    const float* tb  = (const float*)d_in[6];
    const float* lmw = (const float*)d_in[7];
    const float* lmb = (const float*)d_in[8];
    const float* lsw = (const float*)d_in[9];
    const float* lsb = (const float*)d_in[10];
    const float* asw = (const float*)d_in[11];
    const float* asb = (const float*)d_in[12];
    const float* adw = (const float*)d_in[13];
    const float* adb = (const float*)d_in[14];
    float* out = (float*)d_out;

    cudaFuncSetAttribute(k_node, cudaFuncAttributeMaxDynamicSharedMemorySize, SM_BYTES);

    k_embed  <<<NN, 64>>>(x, npw);
    k_topk   <<<NN, 256>>>(ml);
    k_zero_deg<<<(NN+255)/256, 256>>>();
    k_deg    <<<(EE+255)/256, 256>>>(fei);
    k_scan   <<<1, 1024>>>();
    k_scatter<<<(EE+255)/256, 256>>>(fei, fea, ml);
    k_node   <<<NN, 256, SM_BYTES>>>(x, tw, tb, lmw, lmb, lsw, lsb, asw, asb, adw, adb, out);
    k_aggr   <<<NN, 256>>>(out);
}

// round 3
// speedup vs baseline: 4.2332x; 2.6667x over previous
#include <cuda_runtime.h>
#include <math.h>

#define NN 2000
#define TT 64
#define HH 64
#define KK 10
#define PD 32
#define EF 32000
#define EK (NN*KK)
#define EE (EF+EK)
#define RPB 8     // topk rows per block

// ---------------- scratch (static __device__, no allocation) ----------------
__device__ float g_e[NN*PD];          // normalized embeddings
__device__ int   g_knn_dst[EK];
__device__ float g_knn_w[EK];         // vals * alpha
__device__ int   g_deg[NN];
__device__ int   g_rowstart[NN+1];
__device__ int   g_cursor[NN];
__device__ int   g_csr_src[EE];
__device__ float g_csr_w[EE];
__device__ float g_y[(size_t)NN*TT*HH];   // xt @ Wmsg^T + b  (32 MB, L2-resident)
__device__ float g_p[NN*TT];          // xt . att_src + b
__device__ float g_q[NN*TT];          // xt . att_dst + b

// ---------------- K1: x_agg -> e (normalized) ----------------
__global__ void k_embed(const float* __restrict__ x, const float* __restrict__ npw) {
    int n = blockIdx.x; int h = threadIdx.x;      // 64 threads
    __shared__ float xa[HH];
    __shared__ float ev[PD];
    const float* xp = x + (size_t)n*TT*HH + h;
    float s = 0.f;
    #pragma unroll
    for (int t = 0; t < TT; t++) s += xp[t*HH];
    xa[h] = s * (1.0f/TT);
    __syncthreads();
    if (h < PD) {
        float acc = 0.f;
        #pragma unroll
        for (int c = 0; c < HH; c++) acc += xa[c] * npw[h*HH + c];
        ev[h] = acc;
    }
    __syncthreads();
    if (h < PD) {
        float v = ev[h];
        float ss = v*v;
        #pragma unroll
        for (int o = 16; o > 0; o >>= 1) ss += __shfl_xor_sync(0xffffffffu, ss, o);
        float nrm = fmaxf(sqrtf(ss), 1e-12f);
        g_e[n*PD + h] = v / nrm;
    }
}

// ---------------- K2: 8 rows per block, warp-per-row top-(K+1) ----------------
// dyn smem: sim[RPB*NN] + ei[RPB*PD]
#define TK_SM_FLOATS (RPB*NN + RPB*PD)
#define TK_SM_BYTES  (TK_SM_FLOATS*4)
__global__ void __launch_bounds__(256) k_topk(const float* __restrict__ mix_logit) {
    extern __shared__ float smt[];
    float* sim = smt;
    float* ei  = smt + RPB*NN;
    int i0 = blockIdx.x * RPB;
    int tid = threadIdx.x;

    for (int idx = tid; idx < RPB*PD; idx += 256) ei[idx] = g_e[i0*PD + idx];
    __syncthreads();

    // compute sim[r][j] for 8 rows
    for (int j = tid; j < NN; j += 256) {
        const float4* ej = (const float4*)(g_e + j*PD);
        float4 ev[8];
        #pragma unroll
        for (int c = 0; c < 8; c++) ev[c] = ej[c];
        #pragma unroll
        for (int r = 0; r < RPB; r++) {
            const float4* er = (const float4*)(ei + r*PD);
            float dsum = 0.f;
            #pragma unroll
            for (int c = 0; c < 8; c++) {
                float4 e4 = er[c];
                dsum += ev[c].x*e4.x + ev[c].y*e4.y + ev[c].z*e4.z + ev[c].w*e4.w;
            }
            sim[r*NN + j] = dsum;
        }
    }
    __syncthreads();

    float alpha = 1.f/(1.f + expf(-mix_logit[0]));
    int w = tid >> 5, lane = tid & 31;
    int i = i0 + w;
    float* simr = sim + w*NN;
    for (int k = 0; k <= KK; k++) {
        float bv = -INFINITY; int bi = NN;
        for (int j = lane; j < NN; j += 32) {
            float v = simr[j];
            if (v > bv || (v == bv && j < bi)) { bv = v; bi = j; }
        }
        #pragma unroll
        for (int off = 16; off > 0; off >>= 1) {
            float ov = __shfl_down_sync(0xffffffffu, bv, off);
            int   oi = __shfl_down_sync(0xffffffffu, bi, off);
            if (ov > bv || (ov == bv && oi < bi)) { bv = ov; bi = oi; }
        }
        bi = __shfl_sync(0xffffffffu, bi, 0);
        bv = __shfl_sync(0xffffffffu, bv, 0);
        if (lane == 0) {
            if (k > 0) { g_knn_dst[i*KK + (k-1)] = bi; g_knn_w[i*KK + (k-1)] = bv*alpha; }
            simr[bi] = -INFINITY;
        }
        __syncwarp();
    }
}

// ---------------- CSR build ----------------
__global__ void k_zero_deg() {
    int i = blockIdx.x*blockDim.x + threadIdx.x;
    if (i < NN) g_deg[i] = 0;
}

__global__ void k_deg(const int* __restrict__ fei) {
    int e = blockIdx.x*blockDim.x + threadIdx.x;
    if (e >= EE) return;
    int d = (e < EF) ? fei[EF + e] : g_knn_dst[e - EF];
    atomicAdd(&g_deg[d], 1);
}

__global__ void k_scan() {                         // 1 block, 1024 threads
    __shared__ int a[2048], b[2048];
    int tid = threadIdx.x;
    for (int i = tid; i < 2048; i += 1024) a[i] = (i < NN) ? g_deg[i] : 0;
    __syncthreads();
    int* in = a; int* out = b;
    for (int off = 1; off < 2048; off <<= 1) {
        for (int i = tid; i < 2048; i += 1024)
            out[i] = in[i] + (i >= off ? in[i-off] : 0);
        __syncthreads();
        int* t = in; in = out; out = t;
    }
    for (int i = tid; i <= NN; i += 1024) {
        int rs = (i == 0) ? 0 : in[i-1];
        g_rowstart[i] = rs;
        if (i < NN) g_cursor[i] = rs;
    }
}

__global__ void k_scatter(const int* __restrict__ fei, const float* __restrict__ fea,
                          const float* __restrict__ mix_logit) {
    int e = blockIdx.x*blockDim.x + threadIdx.x;
    if (e >= EE) return;
    float alpha = 1.f/(1.f + expf(-mix_logit[0]));
    int s, d; float w;
    if (e < EF) { s = fei[e]; d = fei[EF + e]; w = fea[e]*(1.f - alpha); }
    else { int ke = e - EF; s = ke / KK; d = g_knn_dst[ke]; w = g_knn_w[ke]; }
    int pos = atomicAdd(&g_cursor[d], 1);
    g_csr_src[pos] = s; g_csr_w[pos] = w;
}

// ---------------- K3: fused tconv -> (y, p, q) + self term (float4) ----------------
#define XS_OFF   0
#define XTS_OFF  ((TT+2)*HH)
#define WB_OFF   (XTS_OFF + TT*HH)
#define SM_FLOATS (WB_OFF + 192*65)
#define SM_BYTES  (SM_FLOATS*4)

__global__ void __launch_bounds__(256) k_node(
    const float* __restrict__ x,
    const float* __restrict__ tw,  const float* __restrict__ tb,
    const float* __restrict__ lmw, const float* __restrict__ lmb,
    const float* __restrict__ lsw, const float* __restrict__ lsb,
    const float* __restrict__ asw, const float* __restrict__ asb,
    const float* __restrict__ adw, const float* __restrict__ adb,
    float* __restrict__ out)
{
    extern __shared__ float sm[];
    float* xs  = sm + XS_OFF;
    float* xts = sm + XTS_OFF;
    float* wb  = sm + WB_OFF;
    const float4* xs4  = (const float4*)xs;
    const float4* xts4 = (const float4*)xts;

    int n = blockIdx.x;
    int tid = threadIdx.x;
    int o = tid & 63, tc = tid >> 6;
    int base = tc * 16;

    // phase 1: load x (halo) + stage lsw transposed
    const float* xn = x + (size_t)n*TT*HH;
    for (int idx = tid; idx < TT*HH; idx += 256) xs[idx + HH] = xn[idx];
    for (int idx = tid; idx < HH; idx += 256) { xs[idx] = 0.f; xs[(TT+1)*HH + idx] = 0.f; }
    #pragma unroll
    for (int it = 0; it < 16; it++) {
        int idx = it*256 + tid;
        int oo = idx >> 6, ii = idx & 63;
        wb[ii*65 + oo] = lsw[idx];
    }
    __syncthreads();

    float acc[16];

    // phase 2: self term -> out
    float sb = lsb[o];
    #pragma unroll
    for (int tt = 0; tt < 16; tt++) acc[tt] = sb;
    for (int i4 = 0; i4 < 16; i4++) {
        float wx = wb[(i4*4+0)*65 + o];
        float wy = wb[(i4*4+1)*65 + o];
        float wz = wb[(i4*4+2)*65 + o];
        float ww = wb[(i4*4+3)*65 + o];
        #pragma unroll
        for (int tt = 0; tt < 16; tt++) {
            float4 xv = xs4[(base+tt+1)*16 + i4];
            acc[tt] += xv.x*wx + xv.y*wy + xv.z*wz + xv.w*ww;
        }
    }
    float* op = out + (size_t)n*TT*HH;
    #pragma unroll
    for (int tt = 0; tt < 16; tt++) op[(base+tt)*HH + o] = acc[tt];
    __syncthreads();

    // phase 3: stage tconv weights transposed: wb[(i*3+k)*65 + o]
    #pragma unroll
    for (int it = 0; it < 48; it++) {
        int idx = it*256 + tid;
        int oo = idx / 192, rr = idx - oo*192;
        wb[rr*65 + oo] = tw[idx];
    }
    __syncthreads();

    // phase 4: temporal conv
    #pragma unroll
    for (int tt = 0; tt < 16; tt++) acc[tt] = 0.f;
    for (int i4 = 0; i4 < 16; i4++) {
        int i = i4*4;
        float w0x = wb[((i+0)*3+0)*65 + o], w1x = wb[((i+0)*3+1)*65 + o], w2x = wb[((i+0)*3+2)*65 + o];
        float w0y = wb[((i+1)*3+0)*65 + o], w1y = wb[((i+1)*3+1)*65 + o], w2y = wb[((i+1)*3+2)*65 + o];
        float w0z = wb[((i+2)*3+0)*65 + o], w1z = wb[((i+2)*3+1)*65 + o], w2z = wb[((i+2)*3+2)*65 + o];
        float w0w = wb[((i+3)*3+0)*65 + o], w1w = wb[((i+3)*3+1)*65 + o], w2w = wb[((i+3)*3+2)*65 + o];
        float4 r0 = xs4[(base+0)*16 + i4];
        float4 r1 = xs4[(base+1)*16 + i4];
        #pragma unroll
        for (int tt = 0; tt < 16; tt++) {
            float4 r2 = xs4[(base+tt+2)*16 + i4];
            acc[tt] += r0.x*w0x + r0.y*w0y + r0.z*w0z + r0.w*w0w
                     + r1.x*w1x + r1.y*w1y + r1.z*w1z + r1.w*w1w
                     + r2.x*w2x + r2.y*w2y + r2.z*w2z + r2.w*w2w;
            r0 = r1; r1 = r2;
        }
    }
    float bo = tb[o];
    #pragma unroll
    for (int tt = 0; tt < 16; tt++) xts[(base+tt)*HH + o] = acc[tt] + bo;
    __syncthreads();

    // phase 5: stage lmw transposed
    #pragma unroll
    for (int it = 0; it < 16; it++) {
        int idx = it*256 + tid;
        int oo = idx >> 6, ii = idx & 63;
        wb[ii*65 + oo] = lmw[idx];
    }
    __syncthreads();

    // phase 6: y = xt @ Wmsg^T + b
    float yb = lmb[o];
    #pragma unroll
    for (int tt = 0; tt < 16; tt++) acc[tt] = yb;
    for (int i4 = 0; i4 < 16; i4++) {
        float wx = wb[(i4*4+0)*65 + o];
        float wy = wb[(i4*4+1)*65 + o];
        float wz = wb[(i4*4+2)*65 + o];
        float ww = wb[(i4*4+3)*65 + o];
        #pragma unroll
        for (int tt = 0; tt < 16; tt++) {
            float4 xv = xts4[(base+tt)*16 + i4];
            acc[tt] += xv.x*wx + xv.y*wy + xv.z*wz + xv.w*ww;
        }
    }
    float* yp = g_y + (size_t)n*TT*HH;
    #pragma unroll
    for (int tt = 0; tt < 16; tt++) yp[(base+tt)*HH + o] = acc[tt];

    // phase 7: p, q reductions
    int warp = tid >> 5, lane = tid & 31;
    float asb0 = asb[0], adb0 = adb[0];
    float aw1 = asw[lane], aw2 = asw[lane+32];
    float dw1 = adw[lane], dw2 = adw[lane+32];
    for (int tt = 0; tt < 8; tt++) {
        int t = warp*8 + tt;
        float v1 = xts[t*HH + lane], v2 = xts[t*HH + lane + 32];
        float pp = v1*aw1 + v2*aw2;
        float qq = v1*dw1 + v2*dw2;
        #pragma unroll
        for (int off = 16; off > 0; off >>= 1) {
            pp += __shfl_down_sync(0xffffffffu, pp, off);
            qq += __shfl_down_sync(0xffffffffu, qq, off);
        }
        if (lane == 0) { g_p[n*TT + t] = pp + asb0; g_q[n*TT + t] = qq + adb0; }
    }
}

// ---------------- K4: per-dst softmax + aggregation (register accum, chunked) ----------------
#define CH 16
__global__ void __launch_bounds__(256) k_aggr(float* __restrict__ out) {
    __shared__ float coefw[CH*TT];
    __shared__ int   srcs[CH];
    __shared__ float ws[CH];
    __shared__ float qv[TT];
    __shared__ float ms[TT];
    __shared__ float mpart[4*TT];
    __shared__ float zpart[4*TT];
    __shared__ float zinv[TT];

    int d = blockIdx.x, tid = threadIdx.x;
    int t = tid & 63, q = tid >> 6;
    int r0 = g_rowstart[d], r1 = g_rowstart[d+1];
    int deg = r1 - r0;
    if (tid < TT) qv[tid] = g_q[d*TT + tid];
    __syncthreads();
    float qvt = qv[t];

    // pass 1: per-t max, 4-way parallel over edges
    float m = -INFINITY;
    for (int e = r0 + q; e < r1; e += 4) {
        int s = g_csr_src[e];
        float a = g_p[s*TT + t] + qvt;
        a = a > 0.f ? a : 0.2f*a;
        m = fmaxf(m, a);
    }
    mpart[q*TT + t] = m;
    __syncthreads();
    if (tid < TT) {
        ms[t] = fmaxf(fmaxf(mpart[t], mpart[TT+t]), fmaxf(mpart[2*TT+t], mpart[3*TT+t]));
    }
    __syncthreads();
    float mt = ms[t];

    float4 a0 = {0,0,0,0}, a1 = {0,0,0,0}, a2 = {0,0,0,0}, a3 = {0,0,0,0};
    float zloc = 0.f;
    int t0 = tid >> 4;                      // acc_k covers t = t0 + 16k
    const float4* Y4 = (const float4*)g_y;

    for (int c0 = r0; c0 < r1; c0 += CH) {
        int cn = min(CH, r1 - c0);
        if (tid < cn) { srcs[tid] = g_csr_src[c0+tid]; ws[tid] = g_csr_w[c0+tid]; }
        __syncthreads();
        // phase A: coefs for (ee = q+4k, t)
        #pragma unroll
        for (int k = 0; k < 4; k++) {
            int ee = q + 4*k;
            if (ee < cn) {
                int s = srcs[ee];
                float a = g_p[s*TT + t] + qvt;
                a = a > 0.f ? a : 0.2f*a;
                float cc = __expf(a - mt);
                zloc += cc;
                coefw[ee*TT + t] = cc * ws[ee];
            }
        }
        __syncthreads();
        // phase B: register accumulation
        for (int ee = 0; ee < cn; ee++) {
            const float4* ys = Y4 + (size_t)srcs[ee]*(TT*HH/4);
            float c0f = coefw[ee*TT + t0];
            float c1f = coefw[ee*TT + t0 + 16];
            float c2f = coefw[ee*TT + t0 + 32];
            float c3f = coefw[ee*TT + t0 + 48];
            float4 y0 = ys[tid], y1 = ys[tid+256], y2 = ys[tid+512], y3 = ys[tid+768];
            a0.x += c0f*y0.x; a0.y += c0f*y0.y; a0.z += c0f*y0.z; a0.w += c0f*y0.w;
            a1.x += c1f*y1.x; a1.y += c1f*y1.y; a1.z += c1f*y1.z; a1.w += c1f*y1.w;
            a2.x += c2f*y2.x; a2.y += c2f*y2.y; a2.z += c2f*y2.z; a2.w += c2f*y2.w;
            a3.x += c3f*y3.x; a3.y += c3f*y3.y; a3.z += c3f*y3.z; a3.w += c3f*y3.w;
        }
        __syncthreads();
    }

    zpart[q*TT + t] = zloc;
    __syncthreads();
    if (tid < TT) {
        float z = zpart[t] + zpart[TT+t] + zpart[2*TT+t] + zpart[3*TT+t];
        zinv[t] = 1.f/(z + 1e-16f);
    }
    __syncthreads();

    if (deg > 0) {
        float4* O4 = (float4*)(out + (size_t)d*TT*HH);
        float i0v = zinv[t0], i1v = zinv[t0+16], i2v = zinv[t0+32], i3v = zinv[t0+48];
        float4 o0 = O4[tid];     o0.x += a0.x*i0v; o0.y += a0.y*i0v; o0.z += a0.z*i0v; o0.w += a0.w*i0v; O4[tid]     = o0;
        float4 o1 = O4[tid+256]; o1.x += a1.x*i1v; o1.y += a1.y*i1v; o1.z += a1.z*i1v; o1.w += a1.w*i1v; O4[tid+256] = o1;
        float4 o2 = O4[tid+512]; o2.x += a2.x*i2v; o2.y += a2.y*i2v; o2.z += a2.z*i2v; o2.w += a2.w*i2v; O4[tid+512] = o2;
        float4 o3 = O4[tid+768]; o3.x += a3.x*i3v; o3.y += a3.y*i3v; o3.z += a3.z*i3v; o3.w += a3.w*i3v; O4[tid+768] = o3;
    }
}

// ---------------- launch ----------------
extern "C" void kernel_launch(void* const* d_in, const int* in_sizes, int n_in,
                              void* d_out, int out_size) {
    const float* x   = (const float*)d_in[0];
    const int*   fei = (const int*)  d_in[1];
    const float* fea = (const float*)d_in[2];
    const float* npw = (const float*)d_in[3];
    const float* ml  = (const float*)d_in[4];
    const float* tw  = (const float*)d_in[5];
    const float* tb  = (const float*)d_in[6];
    const float* lmw = (const float*)d_in[7];
    const float* lmb = (const float*)d_in[8];
    const float* lsw = (const float*)d_in[9];
    const float* lsb = (const float*)d_in[10];
    const float* asw = (const float*)d_in[11];
    const float* asb = (const float*)d_in[12];
    const float* adw = (const float*)d_in[13];
    const float* adb = (const float*)d_in[14];
    float* out = (float*)d_out;

    cudaFuncSetAttribute(k_node, cudaFuncAttributeMaxDynamicSharedMemorySize, SM_BYTES);
    cudaFuncSetAttribute(k_topk, cudaFuncAttributeMaxDynamicSharedMemorySize, TK_SM_BYTES);

    // order chosen so ncu's capture slot (#3) lands on k_node
    k_embed  <<<NN, 64>>>(x, npw);
    k_topk   <<<NN/RPB, 256, TK_SM_BYTES>>>(ml);
    k_zero_deg<<<(NN+255)/256, 256>>>();
    k_node   <<<NN, 256, SM_BYTES>>>(x, tw, tb, lmw, lmb, lsw, lsb, asw, asb, adw, adb, out);
    k_deg    <<<(EE+255)/256, 256>>>(fei);
    k_scan   <<<1, 1024>>>();
    k_scatter<<<(EE+255)/256, 256>>>(fei, fea, ml);
    k_aggr   <<<NN, 256>>>(out);
}

// round 4
// speedup vs baseline: 4.5877x; 1.0838x over previous
#include <cuda_runtime.h>
#include <cuda_fp16.h>
#include <math.h>

#define NN 2000
#define TT 64
#define HH 64
#define KK 10
#define PD 32
#define EF 32000
#define EK (NN*KK)
#define EE (EF+EK)
#define RPB 8     // topk rows per block

// ---------------- scratch (static __device__, no allocation) ----------------
__device__ float g_e[NN*PD];          // normalized embeddings
__device__ int   g_knn_dst[EK];
__device__ float g_knn_w[EK];         // vals * alpha
__device__ int   g_deg[NN];
__device__ int   g_rowstart[NN+1];
__device__ int   g_cursor[NN];
__device__ int   g_csr_src[EE];
__device__ float g_csr_w[EE];
__device__ __half g_yh[(size_t)NN*TT*HH];  // xt @ Wmsg^T + b, fp16 (16MB, L2-resident)
__device__ float g_p[NN*TT];          // xt . att_src + b
__device__ float g_q[NN*TT];          // xt . att_dst + b

// ---------------- packed f32x2 helpers ----------------
__device__ __forceinline__ unsigned long long pk(float lo, float hi) {
    unsigned long long r;
    asm("mov.b64 %0, {%1,%2};" : "=l"(r) : "f"(lo), "f"(hi));
    return r;
}
__device__ __forceinline__ void ffma2(unsigned long long& d, unsigned long long a, unsigned long long b) {
    asm("fma.rn.f32x2 %0, %1, %2, %0;" : "+l"(d) : "l"(a), "l"(b));
}
__device__ __forceinline__ float upk_sum(unsigned long long v) {
    float lo, hi;
    asm("mov.b64 {%0,%1}, %2;" : "=f"(lo), "=f"(hi) : "l"(v));
    return lo + hi;
}

// ---------------- K1: x_agg -> e (normalized) ----------------
__global__ void k_embed(const float* __restrict__ x, const float* __restrict__ npw) {
    int n = blockIdx.x; int h = threadIdx.x;      // 64 threads
    __shared__ float xa[HH];
    __shared__ float ev[PD];
    const float* xp = x + (size_t)n*TT*HH + h;
    float s = 0.f;
    #pragma unroll
    for (int t = 0; t < TT; t++) s += xp[t*HH];
    xa[h] = s * (1.0f/TT);
    __syncthreads();
    if (h < PD) {
        float acc = 0.f;
        #pragma unroll
        for (int c = 0; c < HH; c++) acc += xa[c] * npw[h*HH + c];
        ev[h] = acc;
    }
    __syncthreads();
    if (h < PD) {
        float v = ev[h];
        float ss = v*v;
        #pragma unroll
        for (int o = 16; o > 0; o >>= 1) ss += __shfl_xor_sync(0xffffffffu, ss, o);
        float nrm = fmaxf(sqrtf(ss), 1e-12f);
        g_e[n*PD + h] = v / nrm;
    }
}

// ---------------- K2: 8 rows per block, warp-per-row top-(K+1) ----------------
#define TK_SM_FLOATS (RPB*NN + RPB*PD)
#define TK_SM_BYTES  (TK_SM_FLOATS*4)
__global__ void __launch_bounds__(256) k_topk(const float* __restrict__ mix_logit) {
    extern __shared__ float smt[];
    float* sim = smt;
    float* ei  = smt + RPB*NN;
    int i0 = blockIdx.x * RPB;
    int tid = threadIdx.x;

    for (int idx = tid; idx < RPB*PD; idx += 256) ei[idx] = g_e[i0*PD + idx];
    __syncthreads();

    for (int j = tid; j < NN; j += 256) {
        const float4* ej = (const float4*)(g_e + j*PD);
        float4 ev[8];
        #pragma unroll
        for (int c = 0; c < 8; c++) ev[c] = ej[c];
        #pragma unroll
        for (int r = 0; r < RPB; r++) {
            const float4* er = (const float4*)(ei + r*PD);
            float dsum = 0.f;
            #pragma unroll
            for (int c = 0; c < 8; c++) {
                float4 e4 = er[c];
                dsum += ev[c].x*e4.x + ev[c].y*e4.y + ev[c].z*e4.z + ev[c].w*e4.w;
            }
            sim[r*NN + j] = dsum;
        }
    }
    __syncthreads();

    float alpha = 1.f/(1.f + expf(-mix_logit[0]));
    int w = tid >> 5, lane = tid & 31;
    int i = i0 + w;
    float* simr = sim + w*NN;
    for (int k = 0; k <= KK; k++) {
        float bv = -INFINITY; int bi = NN;
        for (int j = lane; j < NN; j += 32) {
            float v = simr[j];
            if (v > bv || (v == bv && j < bi)) { bv = v; bi = j; }
        }
        #pragma unroll
        for (int off = 16; off > 0; off >>= 1) {
            float ov = __shfl_down_sync(0xffffffffu, bv, off);
            int   oi = __shfl_down_sync(0xffffffffu, bi, off);
            if (ov > bv || (ov == bv && oi < bi)) { bv = ov; bi = oi; }
        }
        bi = __shfl_sync(0xffffffffu, bi, 0);
        bv = __shfl_sync(0xffffffffu, bv, 0);
        if (lane == 0) {
            if (k > 0) { g_knn_dst[i*KK + (k-1)] = bi; g_knn_w[i*KK + (k-1)] = bv*alpha; }
            simr[bi] = -INFINITY;
        }
        __syncwarp();
    }
}

// ---------------- CSR build ----------------
__global__ void k_zero_deg() {
    int i = blockIdx.x*blockDim.x + threadIdx.x;
    if (i < NN) g_deg[i] = 0;
}

__global__ void k_deg(const int* __restrict__ fei) {
    int e = blockIdx.x*blockDim.x + threadIdx.x;
    if (e >= EE) return;
    int d = (e < EF) ? fei[EF + e] : g_knn_dst[e - EF];
    atomicAdd(&g_deg[d], 1);
}

__global__ void k_scan() {                         // 1 block, 1024 threads
    __shared__ int a[2048], b[2048];
    int tid = threadIdx.x;
    for (int i = tid; i < 2048; i += 1024) a[i] = (i < NN) ? g_deg[i] : 0;
    __syncthreads();
    int* in = a; int* out = b;
    for (int off = 1; off < 2048; off <<= 1) {
        for (int i = tid; i < 2048; i += 1024)
            out[i] = in[i] + (i >= off ? in[i-off] : 0);
        __syncthreads();
        int* t = in; in = out; out = t;
    }
    for (int i = tid; i <= NN; i += 1024) {
        int rs = (i == 0) ? 0 : in[i-1];
        g_rowstart[i] = rs;
        if (i < NN) g_cursor[i] = rs;
    }
}

__global__ void k_scatter(const int* __restrict__ fei, const float* __restrict__ fea,
                          const float* __restrict__ mix_logit) {
    int e = blockIdx.x*blockDim.x + threadIdx.x;
    if (e >= EE) return;
    float alpha = 1.f/(1.f + expf(-mix_logit[0]));
    int s, d; float w;
    if (e < EF) { s = fei[e]; d = fei[EF + e]; w = fea[e]*(1.f - alpha); }
    else { int ke = e - EF; s = ke / KK; d = g_knn_dst[ke]; w = g_knn_w[ke]; }
    int pos = atomicAdd(&g_cursor[d], 1);
    g_csr_src[pos] = s; g_csr_w[pos] = w;
}

// ---------------- K3: fused tconv -> (y, p, q) + self term (FFMA2) ----------------
// smem (floats): xs 4224 | xts 4096 | wb 96*65=6240  -> 58240 B, 3 blocks/SM
#define XS_OFF   0
#define XTS_OFF  ((TT+2)*HH)
#define WB_OFF   (XTS_OFF + TT*HH)
#define SM_FLOATS (WB_OFF + 96*65)
#define SM_BYTES  (SM_FLOATS*4)

__global__ void __launch_bounds__(256, 3) k_node(
    const float* __restrict__ x,
    const float* __restrict__ tw,  const float* __restrict__ tb,
    const float* __restrict__ lmw, const float* __restrict__ lmb,
    const float* __restrict__ lsw, const float* __restrict__ lsb,
    const float* __restrict__ asw, const float* __restrict__ asb,
    const float* __restrict__ adw, const float* __restrict__ adb,
    float* __restrict__ out)
{
    extern __shared__ float sm[];
    float* xs  = sm + XS_OFF;
    float* xts = sm + XTS_OFF;
    float* wb  = sm + WB_OFF;
    const ulonglong2* xsu  = (const ulonglong2*)xs;   // 16B granules: 2 packed f32x2
    const ulonglong2* xtsu = (const ulonglong2*)xts;

    int n = blockIdx.x;
    int tid = threadIdx.x;
    int o = tid & 63, tc = tid >> 6;
    int base = tc * 16;

    // phase 1: load x (halo) + stage lsw transposed (pad 65 => conflict-free STS)
    const float* xn = x + (size_t)n*TT*HH;
    for (int idx = tid; idx < TT*HH; idx += 256) xs[idx + HH] = xn[idx];
    for (int idx = tid; idx < HH; idx += 256) { xs[idx] = 0.f; xs[(TT+1)*HH + idx] = 0.f; }
    #pragma unroll
    for (int it = 0; it < 16; it++) {
        int idx = it*256 + tid;
        int oo = idx >> 6, ii = idx & 63;
        wb[ii*65 + oo] = lsw[idx];
    }
    __syncthreads();

    unsigned long long acc2[16];

    // phase 2: self term -> out : x @ Wself^T + b   (packed over i-pairs)
    {
        float sb = lsb[o];
        #pragma unroll
        for (int tt = 0; tt < 16; tt++) acc2[tt] = pk(sb, 0.f);
        #pragma unroll 4
        for (int i4 = 0; i4 < 16; i4++) {
            unsigned long long b0 = pk(wb[(4*i4+0)*65 + o], wb[(4*i4+1)*65 + o]);
            unsigned long long b1 = pk(wb[(4*i4+2)*65 + o], wb[(4*i4+3)*65 + o]);
            #pragma unroll
            for (int tt = 0; tt < 16; tt++) {
                ulonglong2 xv = xsu[(base+tt+1)*16 + i4];
                ffma2(acc2[tt], xv.x, b0);
                ffma2(acc2[tt], xv.y, b1);
            }
        }
        float* op = out + (size_t)n*TT*HH;
        #pragma unroll
        for (int tt = 0; tt < 16; tt++) op[(base+tt)*HH + o] = upk_sum(acc2[tt]);
    }
    __syncthreads();

    // phases 3-6: temporal conv in two i-halves, wb restaged per half
    #pragma unroll
    for (int tt = 0; tt < 16; tt++) acc2[tt] = 0ULL;
    for (int h = 0; h < 2; h++) {
        // stage: wb[j*65+o] = tw[o*192 + 96h + j], j in [0,96)
        #pragma unroll
        for (int it = 0; it < 24; it++) {
            int idx = it*256 + tid;            // [0, 6144)
            int oo = idx / 96, jj = idx - oo*96;
            wb[jj*65 + oo] = tw[oo*192 + 96*h + jj];
        }
        __syncthreads();
        #pragma unroll 2
        for (int i4 = 0; i4 < 8; i4++) {
            int jb = i4*12;
            unsigned long long b00 = pk(wb[(jb+0)*65+o],  wb[(jb+3)*65+o]);
            unsigned long long b01 = pk(wb[(jb+6)*65+o],  wb[(jb+9)*65+o]);
            unsigned long long b10 = pk(wb[(jb+1)*65+o],  wb[(jb+4)*65+o]);
            unsigned long long b11 = pk(wb[(jb+7)*65+o],  wb[(jb+10)*65+o]);
            unsigned long long b20 = pk(wb[(jb+2)*65+o],  wb[(jb+5)*65+o]);
            unsigned long long b21 = pk(wb[(jb+8)*65+o],  wb[(jb+11)*65+o]);
            int ig = h*8 + i4;
            ulonglong2 r0 = xsu[(base+0)*16 + ig];
            ulonglong2 r1 = xsu[(base+1)*16 + ig];
            #pragma unroll
            for (int tt = 0; tt < 16; tt++) {
                ulonglong2 r2 = xsu[(base+tt+2)*16 + ig];
                ffma2(acc2[tt], r0.x, b00); ffma2(acc2[tt], r0.y, b01);
                ffma2(acc2[tt], r1.x, b10); ffma2(acc2[tt], r1.y, b11);
                ffma2(acc2[tt], r2.x, b20); ffma2(acc2[tt], r2.y, b21);
                r0 = r1; r1 = r2;
            }
        }
        __syncthreads();
    }
    {
        float bo = tb[o];
        #pragma unroll
        for (int tt = 0; tt < 16; tt++) xts[(base+tt)*HH + o] = upk_sum(acc2[tt]) + bo;
    }
    __syncthreads();

    // phase 7: stage lmw transposed
    #pragma unroll
    for (int it = 0; it < 16; it++) {
        int idx = it*256 + tid;
        int oo = idx >> 6, ii = idx & 63;
        wb[ii*65 + oo] = lmw[idx];
    }
    __syncthreads();

    // phase 8: y = xt @ Wmsg^T + b  -> g_yh (fp16)
    {
        float yb = lmb[o];
        #pragma unroll
        for (int tt = 0; tt < 16; tt++) acc2[tt] = pk(yb, 0.f);
        #pragma unroll 4
        for (int i4 = 0; i4 < 16; i4++) {
            unsigned long long b0 = pk(wb[(4*i4+0)*65 + o], wb[(4*i4+1)*65 + o]);
            unsigned long long b1 = pk(wb[(4*i4+2)*65 + o], wb[(4*i4+3)*65 + o]);
            #pragma unroll
            for (int tt = 0; tt < 16; tt++) {
                ulonglong2 xv = xtsu[(base+tt)*16 + i4];
                ffma2(acc2[tt], xv.x, b0);
                ffma2(acc2[tt], xv.y, b1);
            }
        }
        __half* yp = g_yh + (size_t)n*TT*HH;
        #pragma unroll
        for (int tt = 0; tt < 16; tt++) yp[(base+tt)*HH + o] = __float2half_rn(upk_sum(acc2[tt]));
    }

    // phase 9: p, q reductions over xts
    int warp = tid >> 5, lane = tid & 31;
    float asb0 = asb[0], adb0 = adb[0];
    float aw1 = asw[lane], aw2 = asw[lane+32];
    float dw1 = adw[lane], dw2 = adw[lane+32];
    for (int tt = 0; tt < 8; tt++) {
        int t = warp*8 + tt;
        float v1 = xts[t*HH + lane], v2 = xts[t*HH + lane + 32];
        float pp = v1*aw1 + v2*aw2;
        float qq = v1*dw1 + v2*dw2;
        #pragma unroll
        for (int off = 16; off > 0; off >>= 1) {
            pp += __shfl_down_sync(0xffffffffu, pp, off);
            qq += __shfl_down_sync(0xffffffffu, qq, off);
        }
        if (lane == 0) { g_p[n*TT + t] = pp + asb0; g_q[n*TT + t] = qq + adb0; }
    }
}

// ---------------- K4: per-dst softmax + aggregation (fp16 y gather) ----------------
#define CH 16
__global__ void __launch_bounds__(256) k_aggr(float* __restrict__ out) {
    __shared__ float coefw[CH*TT];
    __shared__ int   srcs[CH];
    __shared__ float ws[CH];
    __shared__ float qv[TT];
    __shared__ float ms[TT];
    __shared__ float mpart[4*TT];
    __shared__ float zpart[4*TT];
    __shared__ float zinv[TT];

    int d = blockIdx.x, tid = threadIdx.x;
    int t = tid & 63, q = tid >> 6;
    int r0 = g_rowstart[d], r1 = g_rowstart[d+1];
    int deg = r1 - r0;
    if (tid < TT) qv[tid] = g_q[d*TT + tid];
    __syncthreads();
    float qvt = qv[t];

    // pass 1: per-t max, 4-way parallel over edges
    float m = -INFINITY;
    for (int e = r0 + q; e < r1; e += 4) {
        int s = g_csr_src[e];
        float a = g_p[s*TT + t] + qvt;
        a = a > 0.f ? a : 0.2f*a;
        m = fmaxf(m, a);
    }
    mpart[q*TT + t] = m;
    __syncthreads();
    if (tid < TT) {
        ms[t] = fmaxf(fmaxf(mpart[t], mpart[TT+t]), fmaxf(mpart[2*TT+t], mpart[3*TT+t]));
    }
    __syncthreads();
    float mt = ms[t];

    // thread owns 16 output floats: halves-uint4 u0=tid (t0=tid>>3), u1=tid+256 (t0+32)
    float a0[8], a1[8];
    #pragma unroll
    for (int j = 0; j < 8; j++) { a0[j] = 0.f; a1[j] = 0.f; }
    float zloc = 0.f;
    int t0 = tid >> 3;                       // 0..31
    const uint4* Y = (const uint4*)g_yh;     // row stride: TT*HH halves = 512 uint4

    for (int c0 = r0; c0 < r1; c0 += CH) {
        int cn = min(CH, r1 - c0);
        if (tid < cn) { srcs[tid] = g_csr_src[c0+tid]; ws[tid] = g_csr_w[c0+tid]; }
        __syncthreads();
        // phase A: coefs for (ee = q+4k, t)
        #pragma unroll
        for (int k = 0; k < 4; k++) {
            int ee = q + 4*k;
            if (ee < cn) {
                int s = srcs[ee];
                float a = g_p[s*TT + t] + qvt;
                a = a > 0.f ? a : 0.2f*a;
                float cc = __expf(a - mt);
                zloc += cc;
                coefw[ee*TT + t] = cc * ws[ee];
            }
        }
        __syncthreads();
        // phase B: register accumulation from fp16 y
        for (int ee = 0; ee < cn; ee++) {
            const uint4* ys = Y + (size_t)srcs[ee]*512;
            float c0f = coefw[ee*TT + t0];
            float c1f = coefw[ee*TT + t0 + 32];
            uint4 v0 = ys[tid];
            uint4 v1 = ys[tid + 256];
            {
                float2 f;
                f = __half22float2(*(const __half2*)&v0.x); a0[0] += c0f*f.x; a0[1] += c0f*f.y;
                f = __half22float2(*(const __half2*)&v0.y); a0[2] += c0f*f.x; a0[3] += c0f*f.y;
                f = __half22float2(*(const __half2*)&v0.z); a0[4] += c0f*f.x; a0[5] += c0f*f.y;
                f = __half22float2(*(const __half2*)&v0.w); a0[6] += c0f*f.x; a0[7] += c0f*f.y;
                f = __half22float2(*(const __half2*)&v1.x); a1[0] += c1f*f.x; a1[1] += c1f*f.y;
                f = __half22float2(*(const __half2*)&v1.y); a1[2] += c1f*f.x; a1[3] += c1f*f.y;
                f = __half22float2(*(const __half2*)&v1.z); a1[4] += c1f*f.x; a1[5] += c1f*f.y;
                f = __half22float2(*(const __half2*)&v1.w); a1[6] += c1f*f.x; a1[7] += c1f*f.y;
            }
        }
        __syncthreads();
    }

    zpart[q*TT + t] = zloc;
    __syncthreads();
    if (tid < TT) {
        float z = zpart[t] + zpart[TT+t] + zpart[2*TT+t] + zpart[3*TT+t];
        zinv[t] = 1.f/(z + 1e-16f);
    }
    __syncthreads();

    if (deg > 0) {
        float4* O4 = (float4*)(out + (size_t)d*TT*HH);
        float i0v = zinv[t0], i1v = zinv[t0+32];
        float4 o;
        o = O4[tid*2];
        o.x += a0[0]*i0v; o.y += a0[1]*i0v; o.z += a0[2]*i0v; o.w += a0[3]*i0v;
        O4[tid*2] = o;
        o = O4[tid*2+1];
        o.x += a0[4]*i0v; o.y += a0[5]*i0v; o.z += a0[6]*i0v; o.w += a0[7]*i0v;
        O4[tid*2+1] = o;
        o = O4[(tid+256)*2];
        o.x += a1[0]*i1v; o.y += a1[1]*i1v; o.z += a1[2]*i1v; o.w += a1[3]*i1v;
        O4[(tid+256)*2] = o;
        o = O4[(tid+256)*2+1];
        o.x += a1[4]*i1v; o.y += a1[5]*i1v; o.z += a1[6]*i1v; o.w += a1[7]*i1v;
        O4[(tid+256)*2+1] = o;
    }
}

// ---------------- launch ----------------
extern "C" void kernel_launch(void* const* d_in, const int* in_sizes, int n_in,
                              void* d_out, int out_size) {
    const float* x   = (const float*)d_in[0];
    const int*   fei = (const int*)  d_in[1];
    const float* fea = (const float*)d_in[2];
    const float* npw = (const float*)d_in[3];
    const float* ml  = (const float*)d_in[4];
    const float* tw  = (const float*)d_in[5];
    const float* tb  = (const float*)d_in[6];
    const float* lmw = (const float*)d_in[7];
    const float* lmb = (const float*)d_in[8];
    const float* lsw = (const float*)d_in[9];
    const float* lsb = (const float*)d_in[10];
    const float* asw = (const float*)d_in[11];
    const float* asb = (const float*)d_in[12];
    const float* adw = (const float*)d_in[13];
    const float* adb = (const float*)d_in[14];
    float* out = (float*)d_out;

    cudaFuncSetAttribute(k_node, cudaFuncAttributeMaxDynamicSharedMemorySize, SM_BYTES);
    cudaFuncSetAttribute(k_topk, cudaFuncAttributeMaxDynamicSharedMemorySize, TK_SM_BYTES);

    // same order as round 3 (keeps ncu capture slot on k_node)
    k_embed  <<<NN, 64>>>(x, npw);
    k_topk   <<<NN/RPB, 256, TK_SM_BYTES>>>(ml);
    k_zero_deg<<<(NN+255)/256, 256>>>();
    k_node   <<<NN, 256, SM_BYTES>>>(x, tw, tb, lmw, lmb, lsw, lsb, asw, asb, adw, adb, out);
    k_deg    <<<(EE+255)/256, 256>>>(fei);
    k_scan   <<<1, 1024>>>();
    k_scatter<<<(EE+255)/256, 256>>>(fei, fea, ml);
    k_aggr   <<<NN, 256>>>(out);
}

// round 5
// speedup vs baseline: 4.8379x; 1.0545x over previous
#include <cuda_runtime.h>
#include <cuda_fp16.h>
#include <math.h>

#define NN 2000
#define TT 64
#define HH 64
#define KK 10
#define PD 32
#define EF 32000
#define EK (NN*KK)
#define EE (EF+EK)
#define RPB 8     // topk rows per block

// ---------------- scratch (static __device__, no allocation) ----------------
__device__ float g_e[NN*PD];          // normalized embeddings
__device__ int   g_knn_dst[EK];
__device__ float g_knn_w[EK];         // vals * alpha
__device__ int   g_deg[NN];
__device__ int   g_rowstart[NN+1];
__device__ int   g_cursor[NN];
__device__ int   g_csr_src[EE];
__device__ float g_csr_w[EE];
__device__ __half g_yh[(size_t)NN*TT*HH];  // xt @ Wmsg^T + b, fp16 (16MB, L2-resident)
__device__ float g_p[NN*TT];          // xt . att_src + b
__device__ float g_q[NN*TT];          // xt . att_dst + b

// ---------------- packed f32x2 helpers ----------------
__device__ __forceinline__ unsigned long long pk(float lo, float hi) {
    unsigned long long r;
    asm("mov.b64 %0, {%1,%2};" : "=l"(r) : "f"(lo), "f"(hi));
    return r;
}
__device__ __forceinline__ void ffma2(unsigned long long& d, unsigned long long a, unsigned long long b) {
    asm("fma.rn.f32x2 %0, %1, %2, %0;" : "+l"(d) : "l"(a), "l"(b));
}
__device__ __forceinline__ float upk_sum(unsigned long long v) {
    float lo, hi;
    asm("mov.b64 {%0,%1}, %2;" : "=f"(lo), "=f"(hi) : "l"(v));
    return lo + hi;
}

// ---------------- K1: x_agg -> e (normalized) ----------------
__global__ void k_embed(const float* __restrict__ x, const float* __restrict__ npw) {
    int n = blockIdx.x; int h = threadIdx.x;      // 64 threads
    __shared__ float xa[HH];
    __shared__ float ev[PD];
    const float* xp = x + (size_t)n*TT*HH + h;
    float s = 0.f;
    #pragma unroll
    for (int t = 0; t < TT; t++) s += xp[t*HH];
    xa[h] = s * (1.0f/TT);
    __syncthreads();
    if (h < PD) {
        float acc = 0.f;
        #pragma unroll
        for (int c = 0; c < HH; c++) acc += xa[c] * npw[h*HH + c];
        ev[h] = acc;
    }
    __syncthreads();
    if (h < PD) {
        float v = ev[h];
        float ss = v*v;
        #pragma unroll
        for (int o = 16; o > 0; o >>= 1) ss += __shfl_xor_sync(0xffffffffu, ss, o);
        float nrm = fmaxf(sqrtf(ss), 1e-12f);
        g_e[n*PD + h] = v / nrm;
    }
}

// ---------------- K2: 8 rows per block, warp-per-row top-(K+1) ----------------
#define TK_SM_FLOATS (RPB*NN + RPB*PD)
#define TK_SM_BYTES  (TK_SM_FLOATS*4)
__global__ void __launch_bounds__(256) k_topk(const float* __restrict__ mix_logit) {
    extern __shared__ float smt[];
    float* sim = smt;
    float* ei  = smt + RPB*NN;
    int i0 = blockIdx.x * RPB;
    int tid = threadIdx.x;

    for (int idx = tid; idx < RPB*PD; idx += 256) ei[idx] = g_e[i0*PD + idx];
    __syncthreads();

    for (int j = tid; j < NN; j += 256) {
        const float4* ej = (const float4*)(g_e + j*PD);
        float4 ev[8];
        #pragma unroll
        for (int c = 0; c < 8; c++) ev[c] = ej[c];
        #pragma unroll
        for (int r = 0; r < RPB; r++) {
            const float4* er = (const float4*)(ei + r*PD);
            float dsum = 0.f;
            #pragma unroll
            for (int c = 0; c < 8; c++) {
                float4 e4 = er[c];
                dsum += ev[c].x*e4.x + ev[c].y*e4.y + ev[c].z*e4.z + ev[c].w*e4.w;
            }
            sim[r*NN + j] = dsum;
        }
    }
    __syncthreads();

    float alpha = 1.f/(1.f + expf(-mix_logit[0]));
    int w = tid >> 5, lane = tid & 31;
    int i = i0 + w;
    float* simr = sim + w*NN;
    for (int k = 0; k <= KK; k++) {
        float bv = -INFINITY; int bi = NN;
        for (int j = lane; j < NN; j += 32) {
            float v = simr[j];
            if (v > bv || (v == bv && j < bi)) { bv = v; bi = j; }
        }
        #pragma unroll
        for (int off = 16; off > 0; off >>= 1) {
            float ov = __shfl_down_sync(0xffffffffu, bv, off);
            int   oi = __shfl_down_sync(0xffffffffu, bi, off);
            if (ov > bv || (ov == bv && oi < bi)) { bv = ov; bi = oi; }
        }
        bi = __shfl_sync(0xffffffffu, bi, 0);
        bv = __shfl_sync(0xffffffffu, bv, 0);
        if (lane == 0) {
            if (k > 0) { g_knn_dst[i*KK + (k-1)] = bi; g_knn_w[i*KK + (k-1)] = bv*alpha; }
            simr[bi] = -INFINITY;
        }
        __syncwarp();
    }
}

// ---------------- CSR build ----------------
__global__ void k_zero_deg() {
    int i = blockIdx.x*blockDim.x + threadIdx.x;
    if (i < NN) g_deg[i] = 0;
}

__global__ void k_deg(const int* __restrict__ fei) {
    int e = blockIdx.x*blockDim.x + threadIdx.x;
    if (e >= EE) return;
    int d = (e < EF) ? fei[EF + e] : g_knn_dst[e - EF];
    atomicAdd(&g_deg[d], 1);
}

__global__ void k_scan() {                         // 1 block, 1024 threads
    __shared__ int a[2048], b[2048];
    int tid = threadIdx.x;
    for (int i = tid; i < 2048; i += 1024) a[i] = (i < NN) ? g_deg[i] : 0;
    __syncthreads();
    int* in = a; int* out = b;
    for (int off = 1; off < 2048; off <<= 1) {
        for (int i = tid; i < 2048; i += 1024)
            out[i] = in[i] + (i >= off ? in[i-off] : 0);
        __syncthreads();
        int* t = in; in = out; out = t;
    }
    for (int i = tid; i <= NN; i += 1024) {
        int rs = (i == 0) ? 0 : in[i-1];
        g_rowstart[i] = rs;
        if (i < NN) g_cursor[i] = rs;
    }
}

__global__ void k_scatter(const int* __restrict__ fei, const float* __restrict__ fea,
                          const float* __restrict__ mix_logit) {
    int e = blockIdx.x*blockDim.x + threadIdx.x;
    if (e >= EE) return;
    float alpha = 1.f/(1.f + expf(-mix_logit[0]));
    int s, d; float w;
    if (e < EF) { s = fei[e]; d = fei[EF + e]; w = fea[e]*(1.f - alpha); }
    else { int ke = e - EF; s = ke / KK; d = g_knn_dst[ke]; w = g_knn_w[ke]; }
    int pos = atomicAdd(&g_cursor[d], 1);
    g_csr_src[pos] = s; g_csr_w[pos] = w;
}

// ---------------- K3: fused tconv -> (y, p, q) + self term ----------------
// 8tt x 2o register tiling; weights packed float2 in smem (pad 65).
// smem (floats): xs 4224 | xts 4096 | wp 6240  -> 58240 B, 3 blocks/SM
#define XS_OFF   0
#define XTS_OFF  ((TT+2)*HH)
#define WP_OFF   (XTS_OFF + TT*HH)
#define SM_FLOATS (WP_OFF + 6240)
#define SM_BYTES  (SM_FLOATS*4)

__global__ void __launch_bounds__(256, 3) k_node(
    const float* __restrict__ x,
    const float* __restrict__ tw,  const float* __restrict__ tb,
    const float* __restrict__ lmw, const float* __restrict__ lmb,
    const float* __restrict__ lsw, const float* __restrict__ lsb,
    const float* __restrict__ asw, const float* __restrict__ asb,
    const float* __restrict__ adw, const float* __restrict__ adb,
    float* __restrict__ out)
{
    extern __shared__ float sm[];
    float* xs  = sm + XS_OFF;
    float* xts = sm + XTS_OFF;
    float* wpf = sm + WP_OFF;
    float2* wp2 = (float2*)wpf;
    unsigned long long* wpu = (unsigned long long*)wpf;
    const ulonglong2* xsu  = (const ulonglong2*)xs;
    const ulonglong2* xtsu = (const ulonglong2*)xts;

    int n = blockIdx.x;
    int tid = threadIdx.x;
    int o = tid & 31;            // channels o and o+32
    int tc = tid >> 5;           // 8 row-slices
    int base = tc * 8;

    unsigned long long aA[8], aB[8];

    // phase 1: load x (halo) + stage lsw packed: wp2[ip*65+oc] = (w[oc,2ip], w[oc,2ip+1])
    const float* xn = x + (size_t)n*TT*HH;
    for (int idx = tid; idx < TT*HH; idx += 256) xs[idx + HH] = xn[idx];
    for (int idx = tid; idx < HH; idx += 256) { xs[idx] = 0.f; xs[(TT+1)*HH + idx] = 0.f; }
    {
        const float2* w2 = (const float2*)lsw;   // [oc][32] float2, coalesced
        #pragma unroll
        for (int it = 0; it < 8; it++) {
            int idx = it*256 + tid;              // [0, 2048)
            int oc = idx >> 5, ip = idx & 31;
            wp2[ip*65 + oc] = w2[idx];
        }
    }
    __syncthreads();

    // phase 2: self term -> out : x @ Wself^T + b
    {
        #pragma unroll
        for (int tt = 0; tt < 8; tt++) { aA[tt] = 0ULL; aB[tt] = 0ULL; }
        #pragma unroll 4
        for (int ip2 = 0; ip2 < 16; ip2++) {
            unsigned long long wA0 = wpu[(2*ip2)*65 + o];
            unsigned long long wB0 = wpu[(2*ip2)*65 + o + 32];
            unsigned long long wA1 = wpu[(2*ip2+1)*65 + o];
            unsigned long long wB1 = wpu[(2*ip2+1)*65 + o + 32];
            #pragma unroll
            for (int tt = 0; tt < 8; tt++) {
                ulonglong2 xv = xsu[(base+tt+1)*16 + ip2];
                ffma2(aA[tt], xv.x, wA0); ffma2(aA[tt], xv.y, wA1);
                ffma2(aB[tt], xv.x, wB0); ffma2(aB[tt], xv.y, wB1);
            }
        }
        float* op = out + (size_t)n*TT*HH;
        float sbA = lsb[o], sbB = lsb[o+32];
        #pragma unroll
        for (int tt = 0; tt < 8; tt++) {
            op[(base+tt)*HH + o]      = upk_sum(aA[tt]) + sbA;
            op[(base+tt)*HH + o + 32] = upk_sum(aB[tt]) + sbB;
        }
    }

    // phases 3-4: temporal conv in two i-halves
    #pragma unroll
    for (int tt = 0; tt < 8; tt++) { aA[tt] = 0ULL; aB[tt] = 0ULL; }
    for (int h = 0; h < 2; h++) {
        __syncthreads();
        // stage: wp[(k*16+ip)*65 + oc] = (tw[oc,h32+2ip,k], tw[oc,h32+2ip+1,k])
        #pragma unroll
        for (int it = 0; it < 24; it++) {
            int idx = it*256 + tid;              // [0, 6144)
            int oc = idx / 96, j = idx - oc*96;  // j = ilocal*3 + k
            int il = j / 3, k = j - il*3;
            int ip = il >> 1, comp = il & 1;
            wpf[((k*16 + ip)*65 + oc)*2 + comp] = tw[oc*192 + h*96 + j];
        }
        __syncthreads();
        #pragma unroll 2
        for (int ip2 = 0; ip2 < 8; ip2++) {
            int lp0 = 2*ip2, lp1 = 2*ip2+1;
            unsigned long long w0A0 = wpu[(0*16+lp0)*65 + o],      w0A1 = wpu[(0*16+lp1)*65 + o];
            unsigned long long w0B0 = wpu[(0*16+lp0)*65 + o + 32], w0B1 = wpu[(0*16+lp1)*65 + o + 32];
            unsigned long long w1A0 = wpu[(1*16+lp0)*65 + o],      w1A1 = wpu[(1*16+lp1)*65 + o];
            unsigned long long w1B0 = wpu[(1*16+lp0)*65 + o + 32], w1B1 = wpu[(1*16+lp1)*65 + o + 32];
            unsigned long long w2A0 = wpu[(2*16+lp0)*65 + o],      w2A1 = wpu[(2*16+lp1)*65 + o];
            unsigned long long w2B0 = wpu[(2*16+lp0)*65 + o + 32], w2B1 = wpu[(2*16+lp1)*65 + o + 32];
            int ig = h*8 + ip2;
            ulonglong2 r0 = xsu[(base+0)*16 + ig];
            ulonglong2 r1 = xsu[(base+1)*16 + ig];
            #pragma unroll
            for (int tt = 0; tt < 8; tt++) {
                ulonglong2 r2 = xsu[(base+tt+2)*16 + ig];
                ffma2(aA[tt], r0.x, w0A0); ffma2(aA[tt], r0.y, w0A1);
                ffma2(aA[tt], r1.x, w1A0); ffma2(aA[tt], r1.y, w1A1);
                ffma2(aA[tt], r2.x, w2A0); ffma2(aA[tt], r2.y, w2A1);
                ffma2(aB[tt], r0.x, w0B0); ffma2(aB[tt], r0.y, w0B1);
                ffma2(aB[tt], r1.x, w1B0); ffma2(aB[tt], r1.y, w1B1);
                ffma2(aB[tt], r2.x, w2B0); ffma2(aB[tt], r2.y, w2B1);
                r0 = r1; r1 = r2;
            }
        }
    }
    {
        float boA = tb[o], boB = tb[o+32];
        #pragma unroll
        for (int tt = 0; tt < 8; tt++) {
            xts[(base+tt)*HH + o]      = upk_sum(aA[tt]) + boA;
            xts[(base+tt)*HH + o + 32] = upk_sum(aB[tt]) + boB;
        }
    }
    __syncthreads();

    // phase 5: stage lmw packed
    {
        const float2* w2 = (const float2*)lmw;
        #pragma unroll
        for (int it = 0; it < 8; it++) {
            int idx = it*256 + tid;
            int oc = idx >> 5, ip = idx & 31;
            wp2[ip*65 + oc] = w2[idx];
        }
    }
    __syncthreads();

    // phase 6: y = xt @ Wmsg^T + b -> g_yh (fp16)
    {
        #pragma unroll
        for (int tt = 0; tt < 8; tt++) { aA[tt] = 0ULL; aB[tt] = 0ULL; }
        #pragma unroll 4
        for (int ip2 = 0; ip2 < 16; ip2++) {
            unsigned long long wA0 = wpu[(2*ip2)*65 + o];
            unsigned long long wB0 = wpu[(2*ip2)*65 + o + 32];
            unsigned long long wA1 = wpu[(2*ip2+1)*65 + o];
            unsigned long long wB1 = wpu[(2*ip2+1)*65 + o + 32];
            #pragma unroll
            for (int tt = 0; tt < 8; tt++) {
                ulonglong2 xv = xtsu[(base+tt)*16 + ip2];
                ffma2(aA[tt], xv.x, wA0); ffma2(aA[tt], xv.y, wA1);
                ffma2(aB[tt], xv.x, wB0); ffma2(aB[tt], xv.y, wB1);
            }
        }
        __half* yp = g_yh + (size_t)n*TT*HH;
        float ybA = lmb[o], ybB = lmb[o+32];
        #pragma unroll
        for (int tt = 0; tt < 8; tt++) {
            yp[(base+tt)*HH + o]      = __float2half_rn(upk_sum(aA[tt]) + ybA);
            yp[(base+tt)*HH + o + 32] = __float2half_rn(upk_sum(aB[tt]) + ybB);
        }
    }

    // phase 7: p, q reductions over xts
    int warp = tid >> 5, lane = tid & 31;
    float asb0 = asb[0], adb0 = adb[0];
    float aw1 = asw[lane], aw2 = asw[lane+32];
    float dw1 = adw[lane], dw2 = adw[lane+32];
    for (int tt = 0; tt < 8; tt++) {
        int t = warp*8 + tt;
        float v1 = xts[t*HH + lane], v2 = xts[t*HH + lane + 32];
        float pp = v1*aw1 + v2*aw2;
        float qq = v1*dw1 + v2*dw2;
        #pragma unroll
        for (int off = 16; off > 0; off >>= 1) {
            pp += __shfl_down_sync(0xffffffffu, pp, off);
            qq += __shfl_down_sync(0xffffffffu, qq, off);
        }
        if (lane == 0) { g_p[n*TT + t] = pp + asb0; g_q[n*TT + t] = qq + adb0; }
    }
}

// ---------------- K4: per-dst softmax + aggregation (fp16 y gather) ----------------
#define CH 16
__global__ void __launch_bounds__(256) k_aggr(float* __restrict__ out) {
    __shared__ float coefw[CH*TT];
    __shared__ int   srcs[CH];
    __shared__ float ws[CH];
    __shared__ float qv[TT];
    __shared__ float ms[TT];
    __shared__ float mpart[4*TT];
    __shared__ float zpart[4*TT];
    __shared__ float zinv[TT];

    int d = blockIdx.x, tid = threadIdx.x;
    int t = tid & 63, q = tid >> 6;
    int r0 = g_rowstart[d], r1 = g_rowstart[d+1];
    int deg = r1 - r0;
    if (tid < TT) qv[tid] = g_q[d*TT + tid];
    __syncthreads();
    float qvt = qv[t];

    float m = -INFINITY;
    for (int e = r0 + q; e < r1; e += 4) {
        int s = g_csr_src[e];
        float a = g_p[s*TT + t] + qvt;
        a = a > 0.f ? a : 0.2f*a;
        m = fmaxf(m, a);
    }
    mpart[q*TT + t] = m;
    __syncthreads();
    if (tid < TT) {
        ms[t] = fmaxf(fmaxf(mpart[t], mpart[TT+t]), fmaxf(mpart[2*TT+t], mpart[3*TT+t]));
    }
    __syncthreads();
    float mt = ms[t];

    float a0[8], a1[8];
    #pragma unroll
    for (int j = 0; j < 8; j++) { a0[j] = 0.f; a1[j] = 0.f; }
    float zloc = 0.f;
    int t0 = tid >> 3;
    const uint4* Y = (const uint4*)g_yh;

    for (int c0 = r0; c0 < r1; c0 += CH) {
        int cn = min(CH, r1 - c0);
        if (tid < cn) { srcs[tid] = g_csr_src[c0+tid]; ws[tid] = g_csr_w[c0+tid]; }
        __syncthreads();
        #pragma unroll
        for (int k = 0; k < 4; k++) {
            int ee = q + 4*k;
            if (ee < cn) {
                int s = srcs[ee];
                float a = g_p[s*TT + t] + qvt;
                a = a > 0.f ? a : 0.2f*a;
                float cc = __expf(a - mt);
                zloc += cc;
                coefw[ee*TT + t] = cc * ws[ee];
            }
        }
        __syncthreads();
        for (int ee = 0; ee < cn; ee++) {
            const uint4* ys = Y + (size_t)srcs[ee]*512;
            float c0f = coefw[ee*TT + t0];
            float c1f = coefw[ee*TT + t0 + 32];
            uint4 v0 = ys[tid];
            uint4 v1 = ys[tid + 256];
            float2 f;
            f = __half22float2(*(const __half2*)&v0.x); a0[0] += c0f*f.x; a0[1] += c0f*f.y;
            f = __half22float2(*(const __half2*)&v0.y); a0[2] += c0f*f.x; a0[3] += c0f*f.y;
            f = __half22float2(*(const __half2*)&v0.z); a0[4] += c0f*f.x; a0[5] += c0f*f.y;
            f = __half22float2(*(const __half2*)&v0.w); a0[6] += c0f*f.x; a0[7] += c0f*f.y;
            f = __half22float2(*(const __half2*)&v1.x); a1[0] += c1f*f.x; a1[1] += c1f*f.y;
            f = __half22float2(*(const __half2*)&v1.y); a1[2] += c1f*f.x; a1[3] += c1f*f.y;
            f = __half22float2(*(const __half2*)&v1.z); a1[4] += c1f*f.x; a1[5] += c1f*f.y;
            f = __half22float2(*(const __half2*)&v1.w); a1[6] += c1f*f.x; a1[7] += c1f*f.y;
        }
        __syncthreads();
    }

    zpart[q*TT + t] = zloc;
    __syncthreads();
    if (tid < TT) {
        float z = zpart[t] + zpart[TT+t] + zpart[2*TT+t] + zpart[3*TT+t];
        zinv[t] = 1.f/(z + 1e-16f);
    }
    __syncthreads();

    if (deg > 0) {
        float4* O4 = (float4*)(out + (size_t)d*TT*HH);
        float i0v = zinv[t0], i1v = zinv[t0+32];
        float4 o;
        o = O4[tid*2];
        o.x += a0[0]*i0v; o.y += a0[1]*i0v; o.z += a0[2]*i0v; o.w += a0[3]*i0v;
        O4[tid*2] = o;
        o = O4[tid*2+1];
        o.x += a0[4]*i0v; o.y += a0[5]*i0v; o.z += a0[6]*i0v; o.w += a0[7]*i0v;
        O4[tid*2+1] = o;
        o = O4[(tid+256)*2];
        o.x += a1[0]*i1v; o.y += a1[1]*i1v; o.z += a1[2]*i1v; o.w += a1[3]*i1v;
        O4[(tid+256)*2] = o;
        o = O4[(tid+256)*2+1];
        o.x += a1[4]*i1v; o.y += a1[5]*i1v; o.z += a1[6]*i1v; o.w += a1[7]*i1v;
        O4[(tid+256)*2+1] = o;
    }
}

// ---------------- launch ----------------
extern "C" void kernel_launch(void* const* d_in, const int* in_sizes, int n_in,
                              void* d_out, int out_size) {
    const float* x   = (const float*)d_in[0];
    const int*   fei = (const int*)  d_in[1];
    const float* fea = (const float*)d_in[2];
    const float* npw = (const float*)d_in[3];
    const float* ml  = (const float*)d_in[4];
    const float* tw  = (const float*)d_in[5];
    const float* tb  = (const float*)d_in[6];
    const float* lmw = (const float*)d_in[7];
    const float* lmb = (const float*)d_in[8];
    const float* lsw = (const float*)d_in[9];
    const float* lsb = (const float*)d_in[10];
    const float* asw = (const float*)d_in[11];
    const float* asb = (const float*)d_in[12];
    const float* adw = (const float*)d_in[13];
    const float* adb = (const float*)d_in[14];
    float* out = (float*)d_out;

    cudaFuncSetAttribute(k_node, cudaFuncAttributeMaxDynamicSharedMemorySize, SM_BYTES);
    cudaFuncSetAttribute(k_topk, cudaFuncAttributeMaxDynamicSharedMemorySize, TK_SM_BYTES);

    k_embed  <<<NN, 64>>>(x, npw);
    k_topk   <<<NN/RPB, 256, TK_SM_BYTES>>>(ml);
    k_zero_deg<<<(NN+255)/256, 256>>>();
    k_node   <<<NN, 256, SM_BYTES>>>(x, tw, tb, lmw, lmb, lsw, lsb, asw, asb, adw, adb, out);
    k_deg    <<<(EE+255)/256, 256>>>(fei);
    k_scan   <<<1, 1024>>>();
    k_scatter<<<(EE+255)/256, 256>>>(fei, fea, ml);
    k_aggr   <<<NN, 256>>>(out);
}